// round 4
// baseline (speedup 1.0000x reference)
#include <cuda_runtime.h>
#include <cstdint>

// ---------------- problem constants ----------------
#define NW   960          // windows
#define NT   144          // tokens per window
#define DIMM 192          // embedding dim
#define NH   6            // heads
#define HD   32           // head dim
#define NQKV 576          // 3*DIMM
#define MROWS (NW*NT)     // 138240 total tokens
#define QSCALE 0.17677669529663689f   // 32^-0.5
#define BIAS_ELEMS (NH*NT*NT)         // 124416

// ---------------- scratch (static device globals; no allocation) ----------------
__device__ float g_q[NW*NH*NT*HD];     // [w][h][n][d], pre-scaled by QSCALE
__device__ float g_k[NW*NH*NT*HD];     // [w][h][n][d]
__device__ float g_v[NW*NH*NT*HD];     // [w][h][n][d]
__device__ float g_ctx[MROWS*DIMM];    // [w][n][h*32+d]  (attention output)
__device__ float g_bias[BIAS_ELEMS];   // [h][n][m]

// ---------------- kernel 0: expand relative-position bias ----------------
__global__ void bias_expand_kernel(const int* __restrict__ rel,
                                   const float* __restrict__ table) {
    int id = blockIdx.x * 256 + threadIdx.x;
    if (id >= BIAS_ELEMS) return;
    int h  = id / (NT * NT);
    int nm = id - h * (NT * NT);
    g_bias[id] = table[rel[nm] * NH + h];
}

// ---------------- generic SGEMM: C[M,N] = A[M,192] @ B[192,N] + bias ----------------
// BM=128, BN=64, BK=16, 256 threads, 8x4 microtile per thread (strided 16x16 map).
// EPI==0 : QKV projection epilogue (scatter into g_q/g_k/g_v, scale q)
// EPI==1 : output projection epilogue (write dense C)
template <int EPI>
__global__ __launch_bounds__(256)
void sgemm_kernel(const float* __restrict__ A, const float* __restrict__ B,
                  const float* __restrict__ bias, float* __restrict__ C,
                  int ldb) {
    __shared__ float As[16 * 130];   // [k][m], stride 130 (pad: conflict-free)
    __shared__ float Bs[16 * 64];    // [k][n]

    const int tid = threadIdx.x;
    const int tx  = tid & 15;        // col group
    const int ty  = tid >> 4;        // row group
    const int m0  = blockIdx.y * 128;
    const int n0  = blockIdx.x * 64;

    const float* Ap = (EPI == 0) ? A : g_ctx;

    float acc[8][4];
#pragma unroll
    for (int i = 0; i < 8; i++)
#pragma unroll
        for (int j = 0; j < 4; j++) acc[i][j] = 0.f;

    const int ar = tid >> 2;   // 0..63  (A row within pass)
    const int aq = tid & 3;    // 0..3   (A k-quad)
    const int bk = tid >> 4;   // 0..15  (B k row)
    const int bc = tid & 15;   // 0..15  (B col quad)

    for (int k0 = 0; k0 < 192; k0 += 16) {
        // load A tile (128x16), transposed into As[k][m]
#pragma unroll
        for (int p = 0; p < 2; p++) {
            const int row = ar + 64 * p;
            float4 a = *(const float4*)&Ap[(size_t)(m0 + row) * 192 + k0 + aq * 4];
            As[(aq * 4 + 0) * 130 + row] = a.x;
            As[(aq * 4 + 1) * 130 + row] = a.y;
            As[(aq * 4 + 2) * 130 + row] = a.z;
            As[(aq * 4 + 3) * 130 + row] = a.w;
        }
        // load B tile (16x64)
        float4 b = *(const float4*)&B[(size_t)(k0 + bk) * ldb + n0 + bc * 4];
        *(float4*)&Bs[bk * 64 + bc * 4] = b;
        __syncthreads();

#pragma unroll
        for (int kk = 0; kk < 16; kk++) {
            float af[8], bf[4];
#pragma unroll
            for (int i = 0; i < 8; i++) af[i] = As[kk * 130 + ty + 16 * i];
#pragma unroll
            for (int j = 0; j < 4; j++) bf[j] = Bs[kk * 64 + tx + 16 * j];
#pragma unroll
            for (int i = 0; i < 8; i++)
#pragma unroll
                for (int j = 0; j < 4; j++)
                    acc[i][j] += af[i] * bf[j];
        }
        __syncthreads();
    }

    // epilogue
#pragma unroll
    for (int i = 0; i < 8; i++) {
        const int m = m0 + ty + 16 * i;
#pragma unroll
        for (int j = 0; j < 4; j++) {
            const int n = n0 + tx + 16 * j;
            float v = acc[i][j] + bias[n];
            if (EPI == 0) {
                const int w    = m / NT;
                const int tok  = m - w * NT;
                const int comp = n / DIMM;            // 0=q 1=k 2=v
                const int rem  = n - comp * DIMM;
                const int h    = rem >> 5;
                const int d    = rem & 31;
                const int idx  = (((w * NH + h) * NT + tok) << 5) + d;
                if (comp == 0)      g_q[idx] = v * QSCALE;
                else if (comp == 1) g_k[idx] = v;
                else                g_v[idx] = v;
            } else {
                C[(size_t)m * DIMM + n] = v;
            }
        }
    }
}

// ---------------- fused attention: one block per (window, head) ----------------
// smem: q[144*33] k[144*33] v[144*32] p[144*145]  = 139,968 bytes
__global__ __launch_bounds__(256, 1)
void attn_kernel(const int* __restrict__ mask) {
    extern __shared__ float sm[];
    float* q_s = sm;                       // stride 33 (conflict-free)
    float* k_s = q_s + NT * 33;
    float* v_s = k_s + NT * 33;            // stride 32 (float2-aligned)
    float* p_s = v_s + NT * 32;            // stride 145 (conflict-free)

    const int blk = blockIdx.x;
    const int w   = blk / NH;
    const int h   = blk - w * NH;
    const int tid = threadIdx.x;

    const int base = ((w * NH + h) * NT) << 5;   // offset into g_q/g_k/g_v
    for (int i = tid; i < NT * HD; i += 256) {
        const int n = i >> 5, d = i & 31;
        q_s[n * 33 + d] = g_q[base + i];
        k_s[n * 33 + d] = g_k[base + i];
        v_s[i]          = g_v[base + i];
    }
    __syncthreads();

    // ---- scores: S[n][m] = q[n]·k[m]  (q pre-scaled) ----
    {
        const int tx = tid & 15;   // m group
        const int ty = tid >> 4;   // n group
        float acc[9][9];
#pragma unroll
        for (int i = 0; i < 9; i++)
#pragma unroll
            for (int j = 0; j < 9; j++) acc[i][j] = 0.f;

#pragma unroll 4
        for (int d = 0; d < 32; d++) {
            float qa[9], kb[9];
#pragma unroll
            for (int i = 0; i < 9; i++) qa[i] = q_s[(ty + 16 * i) * 33 + d];
#pragma unroll
            for (int j = 0; j < 9; j++) kb[j] = k_s[(tx + 16 * j) * 33 + d];
#pragma unroll
            for (int i = 0; i < 9; i++)
#pragma unroll
                for (int j = 0; j < 9; j++)
                    acc[i][j] += qa[i] * kb[j];
        }
#pragma unroll
        for (int i = 0; i < 9; i++)
#pragma unroll
            for (int j = 0; j < 9; j++)
                p_s[(ty + 16 * i) * 145 + tx + 16 * j] = acc[i][j];
    }
    __syncthreads();

    // ---- bias + mask + softmax (one warp per row) ----
    {
        const int lane = tid & 31;
        const int wid  = tid >> 5;
        const float* brow_base = g_bias + h * NT * NT;
        const int*   mrow_base = mask + (size_t)w * NT * NT;
#pragma unroll 1
        for (int k = 0; k < 18; k++) {
            const int n = wid + 8 * k;
            float*       pr = p_s + n * 145;
            const float* br = brow_base + n * NT;
            const int*   mr = mrow_base + n * NT;

            float mx = -3.0e38f;
            for (int m = lane; m < NT; m += 32) {
                float s = pr[m] + br[m];
                if (mr[m] == 0) s = -1.0e9f;
                pr[m] = s;
                mx = fmaxf(mx, s);
            }
#pragma unroll
            for (int off = 16; off; off >>= 1)
                mx = fmaxf(mx, __shfl_xor_sync(0xffffffffu, mx, off));

            float sum = 0.f;
            for (int m = lane; m < NT; m += 32) {
                float e = __expf(pr[m] - mx);
                pr[m] = e;
                sum += e;
            }
#pragma unroll
            for (int off = 16; off; off >>= 1)
                sum += __shfl_xor_sync(0xffffffffu, sum, off);

            const float inv = 1.f / sum;
            for (int m = lane; m < NT; m += 32) pr[m] *= inv;
        }
    }
    __syncthreads();

    // ---- PV: out[n][d] = sum_m P[n][m] * v[m][d] ----
    {
        const int dx = tid & 15;        // d pair: d0 = 2*dx
        const int ny = tid >> 4;        // n group
        float o[9][2];
#pragma unroll
        for (int k = 0; k < 9; k++) { o[k][0] = 0.f; o[k][1] = 0.f; }

#pragma unroll 4
        for (int m = 0; m < NT; m++) {
            const float2 vv = *(const float2*)&v_s[m * 32 + dx * 2];
#pragma unroll
            for (int k = 0; k < 9; k++) {
                const float pp = p_s[(ny + 16 * k) * 145 + m];
                o[k][0] += pp * vv.x;
                o[k][1] += pp * vv.y;
            }
        }
#pragma unroll
        for (int k = 0; k < 9; k++) {
            const int n = ny + 16 * k;
            const int oidx = (((w * NT + n) * NH + h) << 5) + dx * 2;
            *(float2*)&g_ctx[oidx] = make_float2(o[k][0], o[k][1]);
        }
    }
}

// ---------------- launch ----------------
extern "C" void kernel_launch(void* const* d_in, const int* in_sizes, int n_in,
                              void* d_out, int out_size) {
    const float* x      = (const float*)d_in[0];
    const int*   mask   = (const int*)  d_in[1];
    const int*   rel    = (const int*)  d_in[2];
    const float* w_qkv  = (const float*)d_in[3];
    const float* b_qkv  = (const float*)d_in[4];
    const float* w_out  = (const float*)d_in[5];
    const float* b_out  = (const float*)d_in[6];
    const float* btab   = (const float*)d_in[7];
    float*       out    = (float*)d_out;

    // Launch on the stream that is actually being captured (per-thread) if a
    // capture is active; otherwise the legacy default stream.
    cudaStream_t stream = cudaStreamLegacy;
    cudaStreamCaptureStatus st = cudaStreamCaptureStatusNone;
    if (cudaStreamIsCapturing(cudaStreamPerThread, &st) == cudaSuccess &&
        st == cudaStreamCaptureStatusActive) {
        stream = cudaStreamPerThread;
    }

    const int ATTN_SMEM = (NT * 33 * 2 + NT * 32 + NT * 145) * (int)sizeof(float); // 139968
    cudaFuncSetAttribute(attn_kernel,
                         cudaFuncAttributeMaxDynamicSharedMemorySize, ATTN_SMEM);

    // 0) bias expansion
    bias_expand_kernel<<<(BIAS_ELEMS + 255) / 256, 256, 0, stream>>>(rel, btab);

    // 1) QKV projection (+ scatter + q scaling)
    {
        dim3 grid(NQKV / 64, MROWS / 128);   // (9, 1080)
        sgemm_kernel<0><<<grid, 256, 0, stream>>>(x, w_qkv, b_qkv, nullptr, NQKV);
    }

    // 2) fused window attention
    attn_kernel<<<NW * NH, 256, ATTN_SMEM, stream>>>(mask);

    // 3) output projection
    {
        dim3 grid(DIMM / 64, MROWS / 128);   // (3, 1080)
        sgemm_kernel<1><<<grid, 256, 0, stream>>>(nullptr, w_out, b_out, out, DIMM);
    }
}